// round 6
// baseline (speedup 1.0000x reference)
#include <cuda_runtime.h>
#include <cuda_bf16.h>
#include <cstdint>

#define D_MODEL 1024
#define NHEAD   16
#define HDIM    64
#define BATCH   4
#define SEQ     2048
#define NTOK    (BATCH*SEQ)

// Scratch (allocation-free per harness rules)
__device__ float g_q[(size_t)NTOK * D_MODEL];
__device__ float g_k[(size_t)NTOK * D_MODEL];
__device__ float g_v[(size_t)NTOK * D_MODEL];
__device__ float g_att[(size_t)NTOK * D_MODEL];

// ---------------------------------------------------------------------------
// helpers
// ---------------------------------------------------------------------------
__device__ __forceinline__ uint32_t smem_u32(const void* p) {
    uint32_t a;
    asm("{ .reg .u64 t; cvta.to.shared.u64 t, %1; cvt.u32.u64 %0, t; }"
        : "=r"(a) : "l"(p));
    return a;
}
__device__ __forceinline__ void ldm_x4(uint32_t r[4], uint32_t addr) {
    asm volatile("ldmatrix.sync.aligned.m8n8.x4.shared.b16 {%0,%1,%2,%3}, [%4];"
                 : "=r"(r[0]), "=r"(r[1]), "=r"(r[2]), "=r"(r[3]) : "r"(addr));
}
__device__ __forceinline__ void ldm_x4_t(uint32_t r[4], uint32_t addr) {
    asm volatile("ldmatrix.sync.aligned.m8n8.x4.trans.shared.b16 {%0,%1,%2,%3}, [%4];"
                 : "=r"(r[0]), "=r"(r[1]), "=r"(r[2]), "=r"(r[3]) : "r"(addr));
}
__device__ __forceinline__ void mma16816(float c[4], const uint32_t a[4],
                                         uint32_t b0, uint32_t b1) {
    asm volatile(
        "mma.sync.aligned.m16n8k16.row.col.f32.bf16.bf16.f32 "
        "{%0,%1,%2,%3}, {%4,%5,%6,%7}, {%8,%9}, {%0,%1,%2,%3};"
        : "+f"(c[0]), "+f"(c[1]), "+f"(c[2]), "+f"(c[3])
        : "r"(a[0]), "r"(a[1]), "r"(a[2]), "r"(a[3]), "r"(b0), "r"(b1));
}
// split pair of fp32 into packed bf16x2 hi and bf16x2 lo
__device__ __forceinline__ void split2(float f0, float f1,
                                       uint32_t& hi, uint32_t& lo) {
    __nv_bfloat162 h = __float22bfloat162_rn(make_float2(f0, f1));
    float2 hf = make_float2(__low2float(h), __high2float(h));
    __nv_bfloat162 l = __float22bfloat162_rn(make_float2(f0 - hf.x, f1 - hf.y));
    hi = *(uint32_t*)&h; lo = *(uint32_t*)&l;
}
// split one float4 into packed-hi (uint2) and packed-lo (uint2) bf16x4
__device__ __forceinline__ void split_f4(float4 v, uint2& hi, uint2& lo) {
    split2(v.x, v.y, hi.x, lo.x);
    split2(v.z, v.w, hi.y, lo.y);
}

// ---------------------------------------------------------------------------
// GEMM: C[8192,1024] = A @ W^T + bias  via bf16x3 mma.sync  (unchanged R4)
// ---------------------------------------------------------------------------
#define LDT     72
#define TILE_B  (128 * LDT * 2)
#define STAGE_B (4 * TILE_B)
#define DSMEM_B (2 * STAGE_B)

__global__ __launch_bounds__(256, 1)
void gemm_bf16x3(const float* __restrict__ A, const float* __restrict__ W,
                 const float* __restrict__ bias, float* __restrict__ C)
{
    extern __shared__ char sm[];
    const uint32_t s0 = smem_u32(sm);

    const int tid  = threadIdx.x;
    const int lane = tid & 31;
    const int wid  = tid >> 5;
    const int bm = blockIdx.y * 128;
    const int bn = blockIdx.x * 128;
    const int wm = (wid >> 2) * 64;
    const int wn = (wid & 3) * 32;

    float acc[4][4][4];
#pragma unroll
    for (int i = 0; i < 4; i++)
#pragma unroll
        for (int j = 0; j < 4; j++)
#pragma unroll
            for (int q = 0; q < 4; q++) acc[i][j][q] = 0.f;

    const uint32_t offA = (uint32_t)(lane & 15) * 144 + (uint32_t)(lane >> 4) * 16;
    const uint32_t offB = (uint32_t)((lane & 7) + ((lane >> 4) & 1) * 8) * 144
                        + (uint32_t)((lane >> 3) & 1) * 16;

    float4 av[8], bv[8];
#pragma unroll
    for (int j = 0; j < 8; j++) {
        int i = tid + j * 256;
        int row = i >> 4, c4 = i & 15;
        av[j] = *(const float4*)(A + (size_t)(bm + row) * D_MODEL + c4 * 4);
        bv[j] = *(const float4*)(W + (size_t)(bn + row) * D_MODEL + c4 * 4);
    }
    {
        char* stg = sm;
#pragma unroll
        for (int j = 0; j < 8; j++) {
            int i = tid + j * 256;
            int row = i >> 4, c4 = i & 15;
            uint32_t ad = (uint32_t)(row * 144 + c4 * 8);
            uint2 hi, lo;
            split_f4(av[j], hi, lo);
            *(uint2*)(stg + 0 * TILE_B + ad) = hi;
            *(uint2*)(stg + 1 * TILE_B + ad) = lo;
            split_f4(bv[j], hi, lo);
            *(uint2*)(stg + 2 * TILE_B + ad) = hi;
            *(uint2*)(stg + 3 * TILE_B + ad) = lo;
        }
    }
    __syncthreads();

    for (int kt = 0; kt < 16; kt++) {
        if (kt < 15) {
#pragma unroll
            for (int j = 0; j < 8; j++) {
                int i = tid + j * 256;
                int row = i >> 4, c4 = i & 15;
                av[j] = *(const float4*)(A + (size_t)(bm + row) * D_MODEL
                                         + (kt + 1) * 64 + c4 * 4);
                bv[j] = *(const float4*)(W + (size_t)(bn + row) * D_MODEL
                                         + (kt + 1) * 64 + c4 * 4);
            }
        }

        const uint32_t sb = s0 + (uint32_t)(kt & 1) * STAGE_B;
        const uint32_t sAh = sb, sAl = sb + TILE_B;
        const uint32_t sBh = sb + 2 * TILE_B, sBl = sb + 3 * TILE_B;

#pragma unroll
        for (int ks = 0; ks < 4; ks++) {
            uint32_t ah[4][4], al[4][4], bh[2][4], bl[2][4];
            const uint32_t ka = (uint32_t)ks * 32;
#pragma unroll
            for (int mt = 0; mt < 4; mt++) {
                uint32_t ra = (uint32_t)((wm + mt * 16) * 144) + offA + ka;
                ldm_x4(ah[mt], sAh + ra);
                ldm_x4(al[mt], sAl + ra);
            }
#pragma unroll
            for (int p = 0; p < 2; p++) {
                uint32_t rb = (uint32_t)((wn + p * 16) * 144) + offB + ka;
                ldm_x4(bh[p], sBh + rb);
                ldm_x4(bl[p], sBl + rb);
            }
#pragma unroll
            for (int mt = 0; mt < 4; mt++)
#pragma unroll
                for (int nt = 0; nt < 4; nt++) {
                    uint32_t h0 = bh[nt >> 1][(nt & 1) * 2];
                    uint32_t h1 = bh[nt >> 1][(nt & 1) * 2 + 1];
                    uint32_t l0 = bl[nt >> 1][(nt & 1) * 2];
                    uint32_t l1 = bl[nt >> 1][(nt & 1) * 2 + 1];
                    mma16816(acc[mt][nt], ah[mt], h0, h1);
                    mma16816(acc[mt][nt], ah[mt], l0, l1);
                    mma16816(acc[mt][nt], al[mt], h0, h1);
                }
        }

        if (kt < 15) {
            char* stg = sm + ((kt + 1) & 1) * STAGE_B;
#pragma unroll
            for (int j = 0; j < 8; j++) {
                int i = tid + j * 256;
                int row = i >> 4, c4 = i & 15;
                uint32_t ad = (uint32_t)(row * 144 + c4 * 8);
                uint2 hi, lo;
                split_f4(av[j], hi, lo);
                *(uint2*)(stg + 0 * TILE_B + ad) = hi;
                *(uint2*)(stg + 1 * TILE_B + ad) = lo;
                split_f4(bv[j], hi, lo);
                *(uint2*)(stg + 2 * TILE_B + ad) = hi;
                *(uint2*)(stg + 3 * TILE_B + ad) = lo;
            }
        }
        __syncthreads();
    }

#pragma unroll
    for (int mt = 0; mt < 4; mt++) {
        int row0 = bm + wm + mt * 16 + (lane >> 2);
#pragma unroll
        for (int nt = 0; nt < 4; nt++) {
            int col = bn + wn + nt * 8 + (lane & 3) * 2;
            float2 b2 = *(const float2*)&bias[col];
            float2 o0 = make_float2(acc[mt][nt][0] + b2.x, acc[mt][nt][1] + b2.y);
            float2 o1 = make_float2(acc[mt][nt][2] + b2.x, acc[mt][nt][3] + b2.y);
            *(float2*)(C + (size_t)row0 * D_MODEL + col) = o0;
            *(float2*)(C + (size_t)(row0 + 8) * D_MODEL + col) = o1;
        }
    }
}

// ---------------------------------------------------------------------------
// Flash attention via bf16x3 mma.sync — R4 algorithm, 256 threads / 8 warps,
// each warp owns 16 q-rows (one m16 tile). BN=64 KV tile. 2 warps/SMSP.
// smem: Qhi/Qlo [128][72]bf16 resident, Khi/Klo/Vhi/Vlo [64][72] per tile.
// ---------------------------------------------------------------------------
#define AQH 0
#define AQL 18432
#define AKH 36864
#define AKL 46080
#define AVH 55296
#define AVL 64512
#define A_SMEM 73728

__global__ __launch_bounds__(256, 1)
void attn_mma(const float* __restrict__ Qg, const float* __restrict__ Kg,
              const float* __restrict__ Vg, float* __restrict__ Og)
{
    extern __shared__ char sm[];
    const uint32_t s0 = smem_u32(sm);

    const int tid  = threadIdx.x;
    const int lane = tid & 31;
    const int wid  = tid >> 5;
    const int qt = blockIdx.x;          // 16 q-tiles
    const int bh = blockIdx.y;          // 64 (b,h)
    const int b = bh >> 4, h = bh & 15;

    const size_t tok0 = (size_t)b * SEQ + qt * 128;
    const float* Qb = Qg + tok0 * D_MODEL + h * 64;
    const float* Kb = Kg + (size_t)b * SEQ * D_MODEL + h * 64;
    const float* Vb = Vg + (size_t)b * SEQ * D_MODEL + h * 64;

    // per-lane ldmatrix offsets
    const uint32_t laneA = (uint32_t)(((lane >> 3) & 1) * 8 + (lane & 7)) * 144
                         + (uint32_t)(lane >> 4) * 16;   // A frags (Q) and V trans
    const uint32_t laneB = (uint32_t)((lane >> 4) * 8 + (lane & 7)) * 144
                         + (uint32_t)((lane >> 3) & 1) * 16;  // B frags (K)
    const uint32_t wq = (uint32_t)wid * 16 * 144;

    // load Q tile (128 x 64 fp32), split into Qhi/Qlo  (256 threads, 8 iters)
#pragma unroll
    for (int j = 0; j < 8; j++) {
        int i = tid + j * 256;
        int row = i >> 4, c4 = i & 15;
        float4 v = *(const float4*)(Qb + (size_t)row * D_MODEL + c4 * 4);
        uint2 hi, lo;
        split_f4(v, hi, lo);
        uint32_t ad = (uint32_t)(row * 144 + c4 * 8);
        *(uint2*)(sm + AQH + ad) = hi;
        *(uint2*)(sm + AQL + ad) = lo;
    }

    float o[8][4];
#pragma unroll
    for (int dn = 0; dn < 8; dn++)
#pragma unroll
        for (int q = 0; q < 4; q++) o[dn][q] = 0.f;
    float mrow[2] = {-1e30f, -1e30f};
    float lrow[2] = {0.f, 0.f};

    const float SC = 0.125f;

    for (int kt = 0; kt < SEQ / 64; kt++) {
        __syncthreads();   // previous tile's smem reads complete
        // load K,V tiles (64 x 64 fp32 each), split  (256 threads, 4 iters)
#pragma unroll
        for (int j = 0; j < 4; j++) {
            int i = tid + j * 256;
            int row = i >> 4, c4 = i & 15;
            size_t gro = (size_t)(kt * 64 + row) * D_MODEL + c4 * 4;
            uint32_t ad = (uint32_t)(row * 144 + c4 * 8);
            uint2 hi, lo;
            split_f4(*(const float4*)(Kb + gro), hi, lo);
            *(uint2*)(sm + AKH + ad) = hi;
            *(uint2*)(sm + AKL + ad) = lo;
            split_f4(*(const float4*)(Vb + gro), hi, lo);
            *(uint2*)(sm + AVH + ad) = hi;
            *(uint2*)(sm + AVL + ad) = lo;
        }
        __syncthreads();

        // ---- S = Q @ K^T (3-pass split)
        float s[8][4];
#pragma unroll
        for (int nt = 0; nt < 8; nt++)
#pragma unroll
            for (int q = 0; q < 4; q++) s[nt][q] = 0.f;

#pragma unroll
        for (int k = 0; k < 4; k++) {
            uint32_t bhf[4][4], blf[4][4];
#pragma unroll
            for (int np = 0; np < 4; np++) {
                uint32_t rb = (uint32_t)(np * 16 * 144) + k * 32 + laneB;
                ldm_x4(bhf[np], s0 + AKH + rb);
                ldm_x4(blf[np], s0 + AKL + rb);
            }
            uint32_t ah[4], al[4];
            uint32_t ra = wq + k * 32 + laneA;
            ldm_x4(ah, s0 + AQH + ra);
            ldm_x4(al, s0 + AQL + ra);
#pragma unroll
            for (int nt = 0; nt < 8; nt++) {
                uint32_t h0 = bhf[nt >> 1][(nt & 1) * 2];
                uint32_t h1 = bhf[nt >> 1][(nt & 1) * 2 + 1];
                uint32_t l0 = blf[nt >> 1][(nt & 1) * 2];
                uint32_t l1 = blf[nt >> 1][(nt & 1) * 2 + 1];
                mma16816(s[nt], ah, h0, h1);
                mma16816(s[nt], ah, l0, l1);
                mma16816(s[nt], al, h0, h1);
            }
        }

        // ---- online softmax in fragments (rows rr = 0,1 within the m16 tile)
        float corr[2];
#pragma unroll
        for (int rr = 0; rr < 2; rr++) {
            int c0 = rr * 2;
            float mx = -1e30f;
#pragma unroll
            for (int nt = 0; nt < 8; nt++)
                mx = fmaxf(mx, fmaxf(s[nt][c0], s[nt][c0 + 1]));
            mx = fmaxf(mx, __shfl_xor_sync(0xffffffffu, mx, 1));
            mx = fmaxf(mx, __shfl_xor_sync(0xffffffffu, mx, 2));
            float mn = fmaxf(mrow[rr], mx);
            corr[rr] = __expf((mrow[rr] - mn) * SC);
            mrow[rr] = mn;
            float rs = 0.f;
#pragma unroll
            for (int nt = 0; nt < 8; nt++) {
                float e0 = __expf((s[nt][c0] - mn) * SC);
                float e1 = __expf((s[nt][c0 + 1] - mn) * SC);
                s[nt][c0] = e0; s[nt][c0 + 1] = e1;
                rs += e0 + e1;
            }
            rs += __shfl_xor_sync(0xffffffffu, rs, 1);
            rs += __shfl_xor_sync(0xffffffffu, rs, 2);
            lrow[rr] = lrow[rr] * corr[rr] + rs;
        }
#pragma unroll
        for (int dn = 0; dn < 8; dn++) {
            o[dn][0] *= corr[0]; o[dn][1] *= corr[0];
            o[dn][2] *= corr[1]; o[dn][3] *= corr[1];
        }

        // ---- O += P @ V (3-pass split, P packed on the fly)
#pragma unroll
        for (int kk = 0; kk < 4; kk++) {
            uint32_t vhf[4][4], vlf[4][4];
#pragma unroll
            for (int dp = 0; dp < 4; dp++) {
                uint32_t rv = (uint32_t)(kk * 16 * 144) + dp * 32 + laneA;
                ldm_x4_t(vhf[dp], s0 + AVH + rv);
                ldm_x4_t(vlf[dp], s0 + AVL + rv);
            }
            uint32_t ah[4], al[4];
            split2(s[2 * kk][0],     s[2 * kk][1],     ah[0], al[0]);
            split2(s[2 * kk][2],     s[2 * kk][3],     ah[1], al[1]);
            split2(s[2 * kk + 1][0], s[2 * kk + 1][1], ah[2], al[2]);
            split2(s[2 * kk + 1][2], s[2 * kk + 1][3], ah[3], al[3]);
#pragma unroll
            for (int dn = 0; dn < 8; dn++) {
                uint32_t h0 = vhf[dn >> 1][(dn & 1) * 2];
                uint32_t h1 = vhf[dn >> 1][(dn & 1) * 2 + 1];
                uint32_t l0 = vlf[dn >> 1][(dn & 1) * 2];
                uint32_t l1 = vlf[dn >> 1][(dn & 1) * 2 + 1];
                mma16816(o[dn], ah, h0, h1);
                mma16816(o[dn], ah, l0, l1);
                mma16816(o[dn], al, h0, h1);
            }
        }
    }

    // ---- epilogue
    float inv0 = 1.f / lrow[0], inv1 = 1.f / lrow[1];
    size_t row0 = tok0 + wid * 16 + (lane >> 2);
#pragma unroll
    for (int dn = 0; dn < 8; dn++) {
        int col = h * 64 + dn * 8 + (lane & 3) * 2;
        float2 o0 = make_float2(o[dn][0] * inv0, o[dn][1] * inv0);
        float2 o1 = make_float2(o[dn][2] * inv1, o[dn][3] * inv1);
        *(float2*)(Og + row0 * D_MODEL + col) = o0;
        *(float2*)(Og + (row0 + 8) * D_MODEL + col) = o1;
    }
}

// ---------------------------------------------------------------------------
extern "C" void kernel_launch(void* const* d_in, const int* in_sizes, int n_in,
                              void* d_out, int out_size)
{
    const float* q  = (const float*)d_in[0];
    const float* k  = (const float*)d_in[1];
    const float* v  = (const float*)d_in[2];
    const float* Wq = (const float*)d_in[3];
    const float* bq = (const float*)d_in[4];
    const float* Wk = (const float*)d_in[5];
    const float* bk = (const float*)d_in[6];
    const float* Wv = (const float*)d_in[7];
    const float* bv = (const float*)d_in[8];
    const float* Wo = (const float*)d_in[9];
    const float* bo = (const float*)d_in[10];
    float* out = (float*)d_out;

    float *gq, *gk, *gv, *ga;
    cudaGetSymbolAddress((void**)&gq, g_q);
    cudaGetSymbolAddress((void**)&gk, g_k);
    cudaGetSymbolAddress((void**)&gv, g_v);
    cudaGetSymbolAddress((void**)&ga, g_att);

    cudaFuncSetAttribute(gemm_bf16x3,
                         cudaFuncAttributeMaxDynamicSharedMemorySize, DSMEM_B);
    cudaFuncSetAttribute(attn_mma,
                         cudaFuncAttributeMaxDynamicSharedMemorySize, A_SMEM);

    dim3 ggrid(D_MODEL / 128, NTOK / 128);   // (8, 64)
    gemm_bf16x3<<<ggrid, 256, DSMEM_B>>>(q, Wq, bq, gq);
    gemm_bf16x3<<<ggrid, 256, DSMEM_B>>>(k, Wk, bk, gk);
    gemm_bf16x3<<<ggrid, 256, DSMEM_B>>>(v, Wv, bv, gv);

    attn_mma<<<dim3(SEQ / 128, BATCH * NHEAD), 256, A_SMEM>>>(gq, gk, gv, ga);

    gemm_bf16x3<<<ggrid, 256, DSMEM_B>>>(ga, Wo, bo, out);
}

// round 7
// speedup vs baseline: 1.1005x; 1.1005x over previous
#include <cuda_runtime.h>
#include <cuda_bf16.h>
#include <cstdint>

#define D_MODEL 1024
#define NHEAD   16
#define HDIM    64
#define BATCH   4
#define SEQ     2048
#define NTOK    (BATCH*SEQ)

// --------------------------- scratch (bf16 split) ---------------------------
#define ACT_N ((size_t)NTOK * D_MODEL)
#define W_N   ((size_t)D_MODEL * D_MODEL)
__device__ __nv_bfloat16 g_qh[ACT_N],  g_ql[ACT_N];
__device__ __nv_bfloat16 g_kh[ACT_N],  g_kl[ACT_N];
__device__ __nv_bfloat16 g_vh[ACT_N],  g_vl[ACT_N];
__device__ __nv_bfloat16 g_Wqh[W_N], g_Wql[W_N], g_Wkh[W_N], g_Wkl[W_N];
__device__ __nv_bfloat16 g_Wvh[W_N], g_Wvl[W_N], g_Woh[W_N], g_Wol[W_N];
__device__ __nv_bfloat16 g_Qph[ACT_N], g_Qpl[ACT_N];
__device__ __nv_bfloat16 g_Kph[ACT_N], g_Kpl[ACT_N];
__device__ __nv_bfloat16 g_Vph[ACT_N], g_Vpl[ACT_N];
__device__ __nv_bfloat16 g_Ath[ACT_N], g_Atl[ACT_N];

// --------------------------------- helpers ----------------------------------
__device__ __forceinline__ uint32_t smem_u32(const void* p) {
    uint32_t a;
    asm("{ .reg .u64 t; cvta.to.shared.u64 t, %1; cvt.u32.u64 %0, t; }"
        : "=r"(a) : "l"(p));
    return a;
}
__device__ __forceinline__ void ldm_x4(uint32_t r[4], uint32_t addr) {
    asm volatile("ldmatrix.sync.aligned.m8n8.x4.shared.b16 {%0,%1,%2,%3}, [%4];"
                 : "=r"(r[0]), "=r"(r[1]), "=r"(r[2]), "=r"(r[3]) : "r"(addr));
}
__device__ __forceinline__ void ldm_x4_t(uint32_t r[4], uint32_t addr) {
    asm volatile("ldmatrix.sync.aligned.m8n8.x4.trans.shared.b16 {%0,%1,%2,%3}, [%4];"
                 : "=r"(r[0]), "=r"(r[1]), "=r"(r[2]), "=r"(r[3]) : "r"(addr));
}
__device__ __forceinline__ void mma16816(float c[4], const uint32_t a[4],
                                         uint32_t b0, uint32_t b1) {
    asm volatile(
        "mma.sync.aligned.m16n8k16.row.col.f32.bf16.bf16.f32 "
        "{%0,%1,%2,%3}, {%4,%5,%6,%7}, {%8,%9}, {%0,%1,%2,%3};"
        : "+f"(c[0]), "+f"(c[1]), "+f"(c[2]), "+f"(c[3])
        : "r"(a[0]), "r"(a[1]), "r"(a[2]), "r"(a[3]), "r"(b0), "r"(b1));
}
__device__ __forceinline__ void split2(float f0, float f1,
                                       uint32_t& hi, uint32_t& lo) {
    __nv_bfloat162 h = __float22bfloat162_rn(make_float2(f0, f1));
    float2 hf = make_float2(__low2float(h), __high2float(h));
    __nv_bfloat162 l = __float22bfloat162_rn(make_float2(f0 - hf.x, f1 - hf.y));
    hi = *(uint32_t*)&h; lo = *(uint32_t*)&l;
}
__device__ __forceinline__ void split_f4(float4 v, uint2& hi, uint2& lo) {
    split2(v.x, v.y, hi.x, lo.x);
    split2(v.z, v.w, hi.y, lo.y);
}
__device__ __forceinline__ void cp16(uint32_t dst, const void* src) {
    asm volatile("cp.async.cg.shared.global [%0], [%1], 16;"
                 :: "r"(dst), "l"(src) : "memory");
}
__device__ __forceinline__ void cp_commit() {
    asm volatile("cp.async.commit_group;" ::: "memory");
}
#define CP_WAIT(n) asm volatile("cp.async.wait_group %0;" :: "n"(n) : "memory")

// ------------------------------ split kernel --------------------------------
__global__ void split_kernel(const float* __restrict__ in,
                             __nv_bfloat16* __restrict__ hi,
                             __nv_bfloat16* __restrict__ lo, int n4)
{
    int i = blockIdx.x * blockDim.x + threadIdx.x;
    int stride = gridDim.x * blockDim.x;
    for (; i < n4; i += stride) {
        float4 v = ((const float4*)in)[i];
        uint2 h, l;
        split_f4(v, h, l);
        ((uint2*)hi)[i] = h;
        ((uint2*)lo)[i] = l;
    }
}

// ---------------------------------------------------------------------------
// GEMM: C[8192,1024] = A @ W^T + bias, bf16x3, cp.async 3-stage pipeline.
// Inputs pre-split bf16 (Ah/Al, Bh/Bl). 256 thr, 8 warps, 64x32 warp tiles.
// Row stride 144B -> conflict-free ldmatrix. Output fp32 or split bf16.
// ---------------------------------------------------------------------------
#define GTILE  18432                 // 128 rows * 144B
#define GSTAGE (4 * GTILE)           // 73728
#define GSMEM  (3 * GSTAGE)          // 221184

template<bool SPLIT_OUT>
__global__ __launch_bounds__(256, 1)
void gemm_bf16(const __nv_bfloat16* __restrict__ Ah_, const __nv_bfloat16* __restrict__ Al_,
               const __nv_bfloat16* __restrict__ Bh_, const __nv_bfloat16* __restrict__ Bl_,
               const float* __restrict__ bias, float* __restrict__ Cf,
               __nv_bfloat16* __restrict__ Ch, __nv_bfloat16* __restrict__ Cl)
{
    extern __shared__ char sm[];
    const uint32_t s0 = smem_u32(sm);

    const int tid  = threadIdx.x;
    const int lane = tid & 31;
    const int wid  = tid >> 5;
    const int bm = blockIdx.y * 128;
    const int bn = blockIdx.x * 128;
    const int wm = (wid >> 2) * 64;
    const int wn = (wid & 3) * 32;

    float acc[4][4][4];
#pragma unroll
    for (int i = 0; i < 4; i++)
#pragma unroll
        for (int j = 0; j < 4; j++)
#pragma unroll
            for (int q = 0; q < 4; q++) acc[i][j][q] = 0.f;

    const uint32_t offA = (uint32_t)(lane & 15) * 144 + (uint32_t)(lane >> 4) * 16;
    const uint32_t offB = (uint32_t)((lane & 7) + ((lane >> 4) & 1) * 8) * 144
                        + (uint32_t)((lane >> 3) & 1) * 16;

    auto issue = [&](int kt) {
        const uint32_t sb = s0 + (uint32_t)(kt % 3) * GSTAGE;
        const int k0 = kt * 64;
#pragma unroll
        for (int j = 0; j < 16; j++) {
            const int tile = j >> 2;
            int c = tid + j * 256;
            int row = (c >> 3) & 127;
            int seg = c & 7;
            const __nv_bfloat16* src;
            if (tile == 0)      src = Ah_ + (size_t)(bm + row) * D_MODEL + k0 + seg * 8;
            else if (tile == 1) src = Al_ + (size_t)(bm + row) * D_MODEL + k0 + seg * 8;
            else if (tile == 2) src = Bh_ + (size_t)(bn + row) * D_MODEL + k0 + seg * 8;
            else                src = Bl_ + (size_t)(bn + row) * D_MODEL + k0 + seg * 8;
            cp16(sb + (uint32_t)tile * GTILE + (uint32_t)(row * 144 + seg * 16), src);
        }
        cp_commit();
    };

    issue(0);
    issue(1);

    for (int kt = 0; kt < 16; kt++) {
        CP_WAIT(1);
        __syncthreads();
        if (kt + 2 < 16) issue(kt + 2);

        const uint32_t sb = s0 + (uint32_t)(kt % 3) * GSTAGE;
        const uint32_t sAh = sb,             sAl = sb + GTILE;
        const uint32_t sBh = sb + 2 * GTILE, sBl = sb + 3 * GTILE;

#pragma unroll
        for (int ks = 0; ks < 4; ks++) {
            uint32_t ah[4][4], al[4][4], bh[2][4], bl[2][4];
            const uint32_t ka = (uint32_t)ks * 32;
#pragma unroll
            for (int mt = 0; mt < 4; mt++) {
                uint32_t ra = (uint32_t)((wm + mt * 16) * 144) + offA + ka;
                ldm_x4(ah[mt], sAh + ra);
                ldm_x4(al[mt], sAl + ra);
            }
#pragma unroll
            for (int p = 0; p < 2; p++) {
                uint32_t rb = (uint32_t)((wn + p * 16) * 144) + offB + ka;
                ldm_x4(bh[p], sBh + rb);
                ldm_x4(bl[p], sBl + rb);
            }
#pragma unroll
            for (int mt = 0; mt < 4; mt++)
#pragma unroll
                for (int nt = 0; nt < 4; nt++) {
                    uint32_t h0 = bh[nt >> 1][(nt & 1) * 2];
                    uint32_t h1 = bh[nt >> 1][(nt & 1) * 2 + 1];
                    uint32_t l0 = bl[nt >> 1][(nt & 1) * 2];
                    uint32_t l1 = bl[nt >> 1][(nt & 1) * 2 + 1];
                    mma16816(acc[mt][nt], ah[mt], h0, h1);
                    mma16816(acc[mt][nt], ah[mt], l0, l1);
                    mma16816(acc[mt][nt], al[mt], h0, h1);
                }
        }
    }

#pragma unroll
    for (int mt = 0; mt < 4; mt++) {
        int row0 = bm + wm + mt * 16 + (lane >> 2);
#pragma unroll
        for (int nt = 0; nt < 4; nt++) {
            int col = bn + wn + nt * 8 + (lane & 3) * 2;
            float2 b2 = *(const float2*)&bias[col];
            float c0 = acc[mt][nt][0] + b2.x, c1 = acc[mt][nt][1] + b2.y;
            float c2 = acc[mt][nt][2] + b2.x, c3 = acc[mt][nt][3] + b2.y;
            if (SPLIT_OUT) {
                uint32_t h, l;
                split2(c0, c1, h, l);
                *(uint32_t*)(Ch + (size_t)row0 * D_MODEL + col) = h;
                *(uint32_t*)(Cl + (size_t)row0 * D_MODEL + col) = l;
                split2(c2, c3, h, l);
                *(uint32_t*)(Ch + (size_t)(row0 + 8) * D_MODEL + col) = h;
                *(uint32_t*)(Cl + (size_t)(row0 + 8) * D_MODEL + col) = l;
            } else {
                *(float2*)(Cf + (size_t)row0 * D_MODEL + col) = make_float2(c0, c1);
                *(float2*)(Cf + (size_t)(row0 + 8) * D_MODEL + col) = make_float2(c2, c3);
            }
        }
    }
}

// ---------------------------------------------------------------------------
// Flash attention — R4 algorithm (128 thr, 4 warps x 32 q-rows, BN=64),
// pre-split bf16 inputs via cp.async 2-stage KV pipeline. 110.6 KB smem
// -> 2 CTAs/SM. Split bf16 output for the Wo GEMM.
// ---------------------------------------------------------------------------
#define AQH 0
#define AQL 18432
#define AKV0 36864
#define AT   9216                     // one 64x144B tile
#define AST  (4 * AT)                 // KH,KL,VH,VL stage = 36864
#define A_SMEM (AKV0 + 2 * AST)       // 110592

__global__ __launch_bounds__(128, 2)
void attn_mma(const __nv_bfloat16* __restrict__ Qh_, const __nv_bfloat16* __restrict__ Ql_,
              const __nv_bfloat16* __restrict__ Kh_, const __nv_bfloat16* __restrict__ Kl_,
              const __nv_bfloat16* __restrict__ Vh_, const __nv_bfloat16* __restrict__ Vl_,
              __nv_bfloat16* __restrict__ Oh_, __nv_bfloat16* __restrict__ Ol_)
{
    extern __shared__ char sm[];
    const uint32_t s0 = smem_u32(sm);

    const int tid  = threadIdx.x;
    const int lane = tid & 31;
    const int wid  = tid >> 5;
    const int qt = blockIdx.x;          // 16 q-tiles
    const int bh = blockIdx.y;          // 64 (b,h)
    const int b = bh >> 4, h = bh & 15;

    const size_t tok0   = (size_t)b * SEQ + qt * 128;
    const size_t kvbase = (size_t)b * SEQ;

    const uint32_t laneA = (uint32_t)(((lane >> 3) & 1) * 8 + (lane & 7)) * 144
                         + (uint32_t)(lane >> 4) * 16;
    const uint32_t laneB = (uint32_t)((lane >> 4) * 8 + (lane & 7)) * 144
                         + (uint32_t)((lane >> 3) & 1) * 16;
    const uint32_t wq = (uint32_t)wid * 32 * 144;

    // KV stage issue: 16 x 16B per thread (4 tiles x 64 rows x 8 segs)
    auto issue_kv = [&](int kt) {
        const uint32_t sb = s0 + AKV0 + (uint32_t)(kt & 1) * AST;
        const size_t rbase = kvbase + (size_t)kt * 64;
#pragma unroll
        for (int j = 0; j < 16; j++) {
            const int tile = j >> 2;
            int c = tid + (j & 3) * 128;     // 0..511
            int row = c >> 3;
            int seg = c & 7;
            size_t go = (rbase + row) * D_MODEL + h * 64 + seg * 8;
            const __nv_bfloat16* src;
            if (tile == 0)      src = Kh_ + go;
            else if (tile == 1) src = Kl_ + go;
            else if (tile == 2) src = Vh_ + go;
            else                src = Vl_ + go;
            cp16(sb + (uint32_t)tile * AT + (uint32_t)(row * 144 + seg * 16), src);
        }
        cp_commit();
    };

    // prologue: Q (both arrays) + KV stage 0 as group 0; KV stage 1 as group 1
#pragma unroll
    for (int j = 0; j < 16; j++) {
        const int arr = j >> 3;              // 0 = hi, 1 = lo
        int c = tid + (j & 7) * 128;         // 0..1023
        int row = c >> 3;
        int seg = c & 7;
        size_t go = (tok0 + row) * D_MODEL + h * 64 + seg * 8;
        const __nv_bfloat16* src = arr ? (Ql_ + go) : (Qh_ + go);
        cp16(s0 + (arr ? AQL : AQH) + (uint32_t)(row * 144 + seg * 16), src);
    }
    {
        const uint32_t sb = s0 + AKV0;
#pragma unroll
        for (int j = 0; j < 16; j++) {
            const int tile = j >> 2;
            int c = tid + (j & 3) * 128;
            int row = c >> 3;
            int seg = c & 7;
            size_t go = (kvbase + row) * D_MODEL + h * 64 + seg * 8;
            const __nv_bfloat16* src;
            if (tile == 0)      src = Kh_ + go;
            else if (tile == 1) src = Kl_ + go;
            else if (tile == 2) src = Vh_ + go;
            else                src = Vl_ + go;
            cp16(sb + (uint32_t)tile * AT + (uint32_t)(row * 144 + seg * 16), src);
        }
    }
    cp_commit();
    issue_kv(1);

    float o[2][8][4];
#pragma unroll
    for (int mt = 0; mt < 2; mt++)
#pragma unroll
        for (int dn = 0; dn < 8; dn++)
#pragma unroll
            for (int q = 0; q < 4; q++) o[mt][dn][q] = 0.f;
    float mrow[4] = {-1e30f, -1e30f, -1e30f, -1e30f};
    float lrow[4] = {0.f, 0.f, 0.f, 0.f};
    const float SC = 0.125f;

    for (int kt = 0; kt < SEQ / 64; kt++) {
        CP_WAIT(1);
        __syncthreads();

        const uint32_t kb = s0 + AKV0 + (uint32_t)(kt & 1) * AST;

        // ---- S = Q @ K^T (3-pass split)
        float s[2][8][4];
#pragma unroll
        for (int mt = 0; mt < 2; mt++)
#pragma unroll
            for (int nt = 0; nt < 8; nt++)
#pragma unroll
                for (int q = 0; q < 4; q++) s[mt][nt][q] = 0.f;

#pragma unroll
        for (int k = 0; k < 4; k++) {
            uint32_t bhf[4][4], blf[4][4];
#pragma unroll
            for (int np = 0; np < 4; np++) {
                uint32_t rb = (uint32_t)(np * 16 * 144) + k * 32 + laneB;
                ldm_x4(bhf[np], kb + rb);            // KH
                ldm_x4(blf[np], kb + AT + rb);       // KL
            }
#pragma unroll
            for (int mt = 0; mt < 2; mt++) {
                uint32_t ah[4], al[4];
                uint32_t ra = wq + (uint32_t)(mt * 16 * 144) + k * 32 + laneA;
                ldm_x4(ah, s0 + AQH + ra);
                ldm_x4(al, s0 + AQL + ra);
#pragma unroll
                for (int nt = 0; nt < 8; nt++) {
                    uint32_t h0 = bhf[nt >> 1][(nt & 1) * 2];
                    uint32_t h1 = bhf[nt >> 1][(nt & 1) * 2 + 1];
                    uint32_t l0 = blf[nt >> 1][(nt & 1) * 2];
                    uint32_t l1 = blf[nt >> 1][(nt & 1) * 2 + 1];
                    mma16816(s[mt][nt], ah, h0, h1);
                    mma16816(s[mt][nt], ah, l0, l1);
                    mma16816(s[mt][nt], al, h0, h1);
                }
            }
        }

        // ---- online softmax in fragments (rows rr = mt*2 + hilo)
        float corr[4];
#pragma unroll
        for (int rr = 0; rr < 4; rr++) {
            int mt = rr >> 1, c0 = (rr & 1) * 2;
            float mx = -1e30f;
#pragma unroll
            for (int nt = 0; nt < 8; nt++)
                mx = fmaxf(mx, fmaxf(s[mt][nt][c0], s[mt][nt][c0 + 1]));
            mx = fmaxf(mx, __shfl_xor_sync(0xffffffffu, mx, 1));
            mx = fmaxf(mx, __shfl_xor_sync(0xffffffffu, mx, 2));
            float mn = fmaxf(mrow[rr], mx);
            corr[rr] = __expf((mrow[rr] - mn) * SC);
            mrow[rr] = mn;
            float rs = 0.f;
#pragma unroll
            for (int nt = 0; nt < 8; nt++) {
                float e0 = __expf((s[mt][nt][c0] - mn) * SC);
                float e1 = __expf((s[mt][nt][c0 + 1] - mn) * SC);
                s[mt][nt][c0] = e0; s[mt][nt][c0 + 1] = e1;
                rs += e0 + e1;
            }
            rs += __shfl_xor_sync(0xffffffffu, rs, 1);
            rs += __shfl_xor_sync(0xffffffffu, rs, 2);
            lrow[rr] = lrow[rr] * corr[rr] + rs;
        }
#pragma unroll
        for (int mt = 0; mt < 2; mt++)
#pragma unroll
            for (int dn = 0; dn < 8; dn++) {
                o[mt][dn][0] *= corr[mt * 2];
                o[mt][dn][1] *= corr[mt * 2];
                o[mt][dn][2] *= corr[mt * 2 + 1];
                o[mt][dn][3] *= corr[mt * 2 + 1];
            }

        // ---- O += P @ V (3-pass split, P packed on the fly)
#pragma unroll
        for (int kk = 0; kk < 4; kk++) {
            uint32_t vhf[4][4], vlf[4][4];
#pragma unroll
            for (int dp = 0; dp < 4; dp++) {
                uint32_t rv = (uint32_t)(kk * 16 * 144) + dp * 32 + laneA;
                ldm_x4_t(vhf[dp], kb + 2 * AT + rv);  // VH
                ldm_x4_t(vlf[dp], kb + 3 * AT + rv);  // VL
            }
#pragma unroll
            for (int mt = 0; mt < 2; mt++) {
                uint32_t ah[4], al[4];
                split2(s[mt][2 * kk][0],     s[mt][2 * kk][1],     ah[0], al[0]);
                split2(s[mt][2 * kk][2],     s[mt][2 * kk][3],     ah[1], al[1]);
                split2(s[mt][2 * kk + 1][0], s[mt][2 * kk + 1][1], ah[2], al[2]);
                split2(s[mt][2 * kk + 1][2], s[mt][2 * kk + 1][3], ah[3], al[3]);
#pragma unroll
                for (int dn = 0; dn < 8; dn++) {
                    uint32_t h0 = vhf[dn >> 1][(dn & 1) * 2];
                    uint32_t h1 = vhf[dn >> 1][(dn & 1) * 2 + 1];
                    uint32_t l0 = vlf[dn >> 1][(dn & 1) * 2];
                    uint32_t l1 = vlf[dn >> 1][(dn & 1) * 2 + 1];
                    mma16816(o[mt][dn], ah, h0, h1);
                    mma16816(o[mt][dn], ah, l0, l1);
                    mma16816(o[mt][dn], al, h0, h1);
                }
            }
        }

        __syncthreads();                       // all reads of buffer kt&1 done
        if (kt + 2 < SEQ / 64) issue_kv(kt + 2);
    }

    // ---- epilogue: normalize, split, store bf16 hi/lo
    float inv[4];
#pragma unroll
    for (int rr = 0; rr < 4; rr++) inv[rr] = 1.f / lrow[rr];
#pragma unroll
    for (int mt = 0; mt < 2; mt++) {
        size_t row0 = tok0 + wid * 32 + mt * 16 + (lane >> 2);
#pragma unroll
        for (int dn = 0; dn < 8; dn++) {
            int col = h * 64 + dn * 8 + (lane & 3) * 2;
            uint32_t hh, ll;
            split2(o[mt][dn][0] * inv[mt * 2], o[mt][dn][1] * inv[mt * 2], hh, ll);
            *(uint32_t*)(Oh_ + row0 * D_MODEL + col) = hh;
            *(uint32_t*)(Ol_ + row0 * D_MODEL + col) = ll;
            split2(o[mt][dn][2] * inv[mt * 2 + 1], o[mt][dn][3] * inv[mt * 2 + 1], hh, ll);
            *(uint32_t*)(Oh_ + (row0 + 8) * D_MODEL + col) = hh;
            *(uint32_t*)(Ol_ + (row0 + 8) * D_MODEL + col) = ll;
        }
    }
}

// ---------------------------------------------------------------------------
extern "C" void kernel_launch(void* const* d_in, const int* in_sizes, int n_in,
                              void* d_out, int out_size)
{
    const float* q  = (const float*)d_in[0];
    const float* k  = (const float*)d_in[1];
    const float* v  = (const float*)d_in[2];
    const float* Wq = (const float*)d_in[3];
    const float* bq = (const float*)d_in[4];
    const float* Wk = (const float*)d_in[5];
    const float* bk = (const float*)d_in[6];
    const float* Wv = (const float*)d_in[7];
    const float* bv = (const float*)d_in[8];
    const float* Wo = (const float*)d_in[9];
    const float* bo = (const float*)d_in[10];
    float* out = (float*)d_out;

    __nv_bfloat16 *qh, *ql, *kh, *kl, *vh, *vl;
    __nv_bfloat16 *Wqh, *Wql, *Wkh, *Wkl, *Wvh, *Wvl, *Woh, *Wol;
    __nv_bfloat16 *Qph, *Qpl, *Kph, *Kpl, *Vph, *Vpl, *Ath, *Atl;
    cudaGetSymbolAddress((void**)&qh, g_qh);   cudaGetSymbolAddress((void**)&ql, g_ql);
    cudaGetSymbolAddress((void**)&kh, g_kh);   cudaGetSymbolAddress((void**)&kl, g_kl);
    cudaGetSymbolAddress((void**)&vh, g_vh);   cudaGetSymbolAddress((void**)&vl, g_vl);
    cudaGetSymbolAddress((void**)&Wqh, g_Wqh); cudaGetSymbolAddress((void**)&Wql, g_Wql);
    cudaGetSymbolAddress((void**)&Wkh, g_Wkh); cudaGetSymbolAddress((void**)&Wkl, g_Wkl);
    cudaGetSymbolAddress((void**)&Wvh, g_Wvh); cudaGetSymbolAddress((void**)&Wvl, g_Wvl);
    cudaGetSymbolAddress((void**)&Woh, g_Woh); cudaGetSymbolAddress((void**)&Wol, g_Wol);
    cudaGetSymbolAddress((void**)&Qph, g_Qph); cudaGetSymbolAddress((void**)&Qpl, g_Qpl);
    cudaGetSymbolAddress((void**)&Kph, g_Kph); cudaGetSymbolAddress((void**)&Kpl, g_Kpl);
    cudaGetSymbolAddress((void**)&Vph, g_Vph); cudaGetSymbolAddress((void**)&Vpl, g_Vpl);
    cudaGetSymbolAddress((void**)&Ath, g_Ath); cudaGetSymbolAddress((void**)&Atl, g_Atl);

    cudaFuncSetAttribute(gemm_bf16<true>,
                         cudaFuncAttributeMaxDynamicSharedMemorySize, GSMEM);
    cudaFuncSetAttribute(gemm_bf16<false>,
                         cudaFuncAttributeMaxDynamicSharedMemorySize, GSMEM);
    cudaFuncSetAttribute(attn_mma,
                         cudaFuncAttributeMaxDynamicSharedMemorySize, A_SMEM);

    const int ACT4 = (int)(ACT_N / 4);
    const int W4   = (int)(W_N / 4);
    split_kernel<<<2048, 256>>>(q, qh, ql, ACT4);
    split_kernel<<<2048, 256>>>(k, kh, kl, ACT4);
    split_kernel<<<2048, 256>>>(v, vh, vl, ACT4);
    split_kernel<<<512, 256>>>(Wq, Wqh, Wql, W4);
    split_kernel<<<512, 256>>>(Wk, Wkh, Wkl, W4);
    split_kernel<<<512, 256>>>(Wv, Wvh, Wvl, W4);
    split_kernel<<<512, 256>>>(Wo, Woh, Wol, W4);

    dim3 ggrid(D_MODEL / 128, NTOK / 128);   // (8, 64)
    gemm_bf16<true><<<ggrid, 256, GSMEM>>>(qh, ql, Wqh, Wql, bq, nullptr, Qph, Qpl);
    gemm_bf16<true><<<ggrid, 256, GSMEM>>>(kh, kl, Wkh, Wkl, bk, nullptr, Kph, Kpl);
    gemm_bf16<true><<<ggrid, 256, GSMEM>>>(vh, vl, Wvh, Wvl, bv, nullptr, Vph, Vpl);

    attn_mma<<<dim3(SEQ / 128, BATCH * NHEAD), 128, A_SMEM>>>(
        Qph, Qpl, Kph, Kpl, Vph, Vpl, Ath, Atl);

    gemm_bf16<false><<<ggrid, 256, GSMEM>>>(Ath, Atl, Woh, Wol, bo, out,
                                            nullptr, nullptr);
}